// round 9
// baseline (speedup 1.0000x reference)
#include <cuda_runtime.h>
#include <math.h>

// ---------------- fast-math row loss (tolerance 1e-3, margin ~5e-8) --------
__device__ __forceinline__ float row_loss(const float* __restrict__ p,
                                          const float* __restrict__ t) {
    float dx = p[0] - t[0];
    float dy = p[1] - t[1];

    float wp = fminf(fmaxf(p[2], 1e-7f), 1e7f);
    float hp = fminf(fmaxf(p[3], 1e-7f), 1e7f);
    float ap = 0.25f * wp * wp;
    float bp = 0.25f * hp * hp;
    float sn, cs;
    __sincosf(p[4], &sn, &cs);           // |r| < pi/2: MUFU path accurate
    float c2 = cs * cs, s2 = sn * sn;
    float p00 = ap * c2 + bp * s2;
    float p11 = ap * s2 + bp * c2;
    float p01 = (ap - bp) * sn * cs;

    float wt = fminf(fmaxf(t[2], 1e-7f), 1e7f);
    float ht = fminf(fmaxf(t[3], 1e-7f), 1e7f);
    float at = 0.25f * wt * wt;
    float bt = 0.25f * ht * ht;
    float snt, cst;
    __sincosf(t[4], &snt, &cst);
    float ct2 = cst * cst, st2 = snt * snt;
    float t00 = at * ct2 + bt * st2;
    float t11 = at * st2 + bt * ct2;
    float t01 = (at - bt) * snt * cst;

    float det_p = p00 * p11 - p01 * p01;
    float det_t = t00 * t11 - t01 * t01;
    float inv_det_t = __fdividef(1.0f, det_t);

    float term1 = (dx * dx * t11 - 2.0f * dx * dy * t01 + dy * dy * t00) * inv_det_t;
    float tr = (t11 * p00 + t00 * p11 - 2.0f * t01 * p01) * inv_det_t;

    float dis = term1 + tr + __logf(__fdividef(det_t, det_p)) - 2.0f;
    float kl = fmaxf(dis, 1e-6f);
    float L = __logf(1.0f + kl);
    return __fdividef(L, 1.0f + L);      // 1 - 1/(1+L), tau = 1
}

// ---------------- coalesced LDG + smem double-buffer pipeline ---------------
// Tile = 256 rows = 320 float4 per stream. Threads load lane-consecutive
// float4 (coalesced: 4 lines per warp LDG.128) one tile ahead; rows are
// redistributed through smem (stride-5 word reads: gcd(5,32)=1, conflict-free).
// One __syncthreads per tile; compute(i) overlaps LDG(i+1) latency.
#define TILE_ROWS 256
#define TILE_V4   320                    // 256*5/4 per stream

__global__ void __launch_bounds__(256, 3)
kld_pipe2_kernel(const float4* __restrict__ pred,
                 const float4* __restrict__ targ,
                 float* __restrict__ out, int ntiles) {
    __shared__ float4 shp[2][TILE_V4];
    __shared__ float4 sht[2][TILE_V4];

    const int tid = threadIdx.x;
    const bool extra = tid < (TILE_V4 - 256);   // tid < 64 loads second slot

    long long tile = blockIdx.x;
    const long long tstr = gridDim.x;

    // ---- load tile 0 into regs ----
    size_t vb = (size_t)tile * TILE_V4;
    float4 pa = __ldcs(&pred[vb + tid]);
    float4 ta = __ldcs(&targ[vb + tid]);
    float4 pb = {}, tb = {};
    if (extra) {
        pb = __ldcs(&pred[vb + 256 + tid]);
        tb = __ldcs(&targ[vb + 256 + tid]);
    }

    // ---- store tile 0 into buffer 0 ----
    shp[0][tid] = pa;  sht[0][tid] = ta;
    if (extra) { shp[0][256 + tid] = pb;  sht[0][256 + tid] = tb; }

    // ---- prefetch tile 1 ----
    long long nt = tile + tstr;
    bool hn = nt < ntiles;
    if (hn) {
        vb = (size_t)nt * TILE_V4;
        pa = __ldcs(&pred[vb + tid]);
        ta = __ldcs(&targ[vb + tid]);
        if (extra) {
            pb = __ldcs(&pred[vb + 256 + tid]);
            tb = __ldcs(&targ[vb + 256 + tid]);
        }
    }
    __syncthreads();

    int buf = 0;
#pragma unroll 1
    while (true) {
        // compute current tile from smem (stride-5 words: conflict-free)
        const float* pf = reinterpret_cast<const float*>(&shp[buf][0]);
        const float* tf = reinterpret_cast<const float*>(&sht[buf][0]);
        float r = row_loss(pf + 5 * tid, tf + 5 * tid);
        __stcs(&out[tile * TILE_ROWS + tid], r);

        if (!hn) break;

        // store prefetched tile into the other buffer (disjoint from buf)
        shp[buf ^ 1][tid] = pa;  sht[buf ^ 1][tid] = ta;
        if (extra) { shp[buf ^ 1][256 + tid] = pb;  sht[buf ^ 1][256 + tid] = tb; }

        // issue loads for the tile after next (lands during next compute)
        tile = nt;
        nt = tile + tstr;
        hn = nt < ntiles;
        if (hn) {
            vb = (size_t)nt * TILE_V4;
            pa = __ldcs(&pred[vb + tid]);
            ta = __ldcs(&targ[vb + tid]);
            if (extra) {
                pb = __ldcs(&pred[vb + 256 + tid]);
                tb = __ldcs(&targ[vb + 256 + tid]);
            }
        }
        __syncthreads();          // stores visible; everyone done with old buf
        buf ^= 1;
    }
}

// Scalar tail for rows not covered by full 256-row tiles (not hit for N=4M).
__global__ void kld_loss_tail_kernel(const float* __restrict__ pred,
                                     const float* __restrict__ targ,
                                     float* __restrict__ out,
                                     int start, int n) {
    int i = start + blockIdx.x * blockDim.x + threadIdx.x;
    if (i >= n) return;
    out[i] = row_loss(pred + 5 * i, targ + 5 * i);
}

extern "C" void kernel_launch(void* const* d_in, const int* in_sizes, int n_in,
                              void* d_out, int out_size) {
    const float* pred = (const float*)d_in[0];
    const float* targ = (const float*)d_in[1];
    float* out = (float*)d_out;

    int n = in_sizes[0] / 5;       // rows
    int ntiles = n / TILE_ROWS;    // 15625 for N=4M
    int rem_start = ntiles * TILE_ROWS;

    if (ntiles > 0) {
        int grid = 152 * 3;        // persistent, 3 CTAs/SM
        if (grid > ntiles) grid = ntiles;
        kld_pipe2_kernel<<<grid, 256>>>(
            (const float4*)pred, (const float4*)targ, out, ntiles);
    }
    if (rem_start < n) {
        int rem = n - rem_start;
        kld_loss_tail_kernel<<<(rem + 127) / 128, 128>>>(pred, targ, out,
                                                         rem_start, n);
    }
}

// round 10
// speedup vs baseline: 1.0643x; 1.0643x over previous
#include <cuda_runtime.h>
#include <cstdint>
#include <math.h>

// ---------------- fast-math row loss (tolerance 1e-3, margin ~5e-8) --------
__device__ __forceinline__ float row_loss(const float* __restrict__ p,
                                          const float* __restrict__ t) {
    float dx = p[0] - t[0];
    float dy = p[1] - t[1];

    float wp = fminf(fmaxf(p[2], 1e-7f), 1e7f);
    float hp = fminf(fmaxf(p[3], 1e-7f), 1e7f);
    float ap = 0.25f * wp * wp;
    float bp = 0.25f * hp * hp;
    float sn, cs;
    __sincosf(p[4], &sn, &cs);           // |r| < pi/2: MUFU path accurate
    float c2 = cs * cs, s2 = sn * sn;
    float p00 = ap * c2 + bp * s2;
    float p11 = ap * s2 + bp * c2;
    float p01 = (ap - bp) * sn * cs;

    float wt = fminf(fmaxf(t[2], 1e-7f), 1e7f);
    float ht = fminf(fmaxf(t[3], 1e-7f), 1e7f);
    float at = 0.25f * wt * wt;
    float bt = 0.25f * ht * ht;
    float snt, cst;
    __sincosf(t[4], &snt, &cst);
    float ct2 = cst * cst, st2 = snt * snt;
    float t00 = at * ct2 + bt * st2;
    float t11 = at * st2 + bt * ct2;
    float t01 = (at - bt) * snt * cst;

    float det_p = p00 * p11 - p01 * p01;
    float det_t = t00 * t11 - t01 * t01;
    float inv_det_t = __fdividef(1.0f, det_t);

    float term1 = (dx * dx * t11 - 2.0f * dx * dy * t01 + dy * dy * t00) * inv_det_t;
    float tr = (t11 * p00 + t00 * p11 - 2.0f * t01 * p01) * inv_det_t;

    float dis = term1 + tr + __logf(__fdividef(det_t, det_p)) - 2.0f;
    float kl = fmaxf(dis, 1e-6f);
    float L = __logf(1.0f + kl);
    return __fdividef(L, 1.0f + L);      // 1 - 1/(1+L), tau = 1
}

// ---------------- warp-private TMA pipelines --------------------------------
// Each WARP owns an independent 4-stage cp.async.bulk ring over 64-row tiles
// (1280 B per stream per stage). No __syncthreads after init — warps never
// wait on each other. TMA bypasses L1tex (no wavefront amplification) and has
// zero per-byte issue cost.
#define WSTAGES   4
#define WTILE_ROWS 64
#define WTILE_BYTES (WTILE_ROWS * 20)        // 1280 B per stream
#define WARPS_PER_CTA 8

__device__ __forceinline__ uint32_t smem_u32(const void* p) {
    return (uint32_t)__cvta_generic_to_shared(p);
}
__device__ __forceinline__ void mbar_init(uint32_t bar, uint32_t count) {
    asm volatile("mbarrier.init.shared.b64 [%0], %1;" :: "r"(bar), "r"(count) : "memory");
}
__device__ __forceinline__ void mbar_expect_tx(uint32_t bar, uint32_t bytes) {
    asm volatile("mbarrier.arrive.expect_tx.shared.b64 _, [%0], %1;"
                 :: "r"(bar), "r"(bytes) : "memory");
}
__device__ __forceinline__ void bulk_ld(uint32_t dst_smem, const void* src,
                                        uint32_t bytes, uint32_t bar) {
    asm volatile(
        "cp.async.bulk.shared::cta.global.mbarrier::complete_tx::bytes "
        "[%0], [%1], %2, [%3];"
        :: "r"(dst_smem), "l"(src), "r"(bytes), "r"(bar) : "memory");
}
__device__ __forceinline__ void mbar_wait(uint32_t bar, uint32_t parity) {
    asm volatile(
        "{\n\t"
        ".reg .pred P;\n\t"
        "WAIT_%=:\n\t"
        "mbarrier.try_wait.parity.acquire.cta.shared::cta.b64 P, [%0], %1, 0x989680;\n\t"
        "@P bra WAIT_DONE_%=;\n\t"
        "bra WAIT_%=;\n\t"
        "WAIT_DONE_%=:\n\t"
        "}"
        :: "r"(bar), "r"(parity) : "memory");
}

__global__ void __launch_bounds__(256, 2)
kld_warptma_kernel(const char* __restrict__ pred, const char* __restrict__ targ,
                   float* __restrict__ out, int ntiles) {
    // per-warp, per-stage buffers: [warp][stage][stream 0=pred 1=targ]
    __shared__ alignas(128) char buf[WARPS_PER_CTA][WSTAGES][2][WTILE_BYTES];
    __shared__ alignas(8) uint64_t mbar[WARPS_PER_CTA][WSTAGES];

    const int tid  = threadIdx.x;
    const int wid  = tid >> 5;
    const int lane = tid & 31;

    if (lane == 0) {
#pragma unroll
        for (int s = 0; s < WSTAGES; s++)
            mbar_init(smem_u32(&mbar[wid][s]), 1);
    }
    __syncthreads();
    if (tid == 0)
        asm volatile("fence.proxy.async.shared::cta;" ::: "memory");
    __syncthreads();   // mbarrier init visible to async proxy, all warps

    const long long gw     = (long long)blockIdx.x * WARPS_PER_CTA + wid;
    const long long nwarps = (long long)gridDim.x * WARPS_PER_CTA;

    // prologue: fill this warp's ring
    if (lane == 0) {
#pragma unroll
        for (int s = 0; s < WSTAGES; s++) {
            long long tile = gw + (long long)s * nwarps;
            if (tile < ntiles) {
                uint32_t bar = smem_u32(&mbar[wid][s]);
                mbar_expect_tx(bar, 2 * WTILE_BYTES);
                bulk_ld(smem_u32(&buf[wid][s][0][0]),
                        pred + tile * WTILE_BYTES, WTILE_BYTES, bar);
                bulk_ld(smem_u32(&buf[wid][s][1][0]),
                        targ + tile * WTILE_BYTES, WTILE_BYTES, bar);
            }
        }
    }

    int j = 0;
    for (long long tile = gw; tile < ntiles; tile += nwarps, j++) {
        int s  = j & (WSTAGES - 1);
        int ph = (j >> 2) & 1;
        mbar_wait(smem_u32(&mbar[wid][s]), ph);

        const float* pf = reinterpret_cast<const float*>(&buf[wid][s][0][0]);
        const float* tf = reinterpret_cast<const float*>(&buf[wid][s][1][0]);
        // 2 rows per lane: row = lane and lane+32 (stride-5 words: conflict-free)
        float r0 = row_loss(pf + 5 * lane,        tf + 5 * lane);
        float r1 = row_loss(pf + 5 * (lane + 32), tf + 5 * (lane + 32));
        long long ob = tile * WTILE_ROWS;
        __stcs(&out[ob + lane],      r0);
        __stcs(&out[ob + lane + 32], r1);

        __syncwarp();                      // all lanes done with stage s
        long long next = tile + (long long)WSTAGES * nwarps;
        if (lane == 0 && next < ntiles) {
            uint32_t bar = smem_u32(&mbar[wid][s]);
            mbar_expect_tx(bar, 2 * WTILE_BYTES);
            bulk_ld(smem_u32(&buf[wid][s][0][0]),
                    pred + next * WTILE_BYTES, WTILE_BYTES, bar);
            bulk_ld(smem_u32(&buf[wid][s][1][0]),
                    targ + next * WTILE_BYTES, WTILE_BYTES, bar);
        }
    }
}

// Scalar tail for rows not covered by full 64-row tiles (not hit for N=4M).
__global__ void kld_loss_tail_kernel(const float* __restrict__ pred,
                                     const float* __restrict__ targ,
                                     float* __restrict__ out,
                                     int start, int n) {
    int i = start + blockIdx.x * blockDim.x + threadIdx.x;
    if (i >= n) return;
    out[i] = row_loss(pred + 5 * i, targ + 5 * i);
}

extern "C" void kernel_launch(void* const* d_in, const int* in_sizes, int n_in,
                              void* d_out, int out_size) {
    const float* pred = (const float*)d_in[0];
    const float* targ = (const float*)d_in[1];
    float* out = (float*)d_out;

    int n = in_sizes[0] / 5;            // rows
    int ntiles = n / WTILE_ROWS;        // 62500 for N=4M
    int rem_start = ntiles * WTILE_ROWS;

    if (ntiles > 0) {
        int grid = 152 * 2;             // persistent, 2 CTAs/SM (smem-capped)
        long long maxg = ((long long)ntiles + WARPS_PER_CTA - 1) / WARPS_PER_CTA;
        if (grid > maxg) grid = (int)maxg;
        kld_warptma_kernel<<<grid, 256>>>((const char*)pred, (const char*)targ,
                                          out, ntiles);
    }
    if (rem_start < n) {
        int rem = n - rem_start;
        kld_loss_tail_kernel<<<(rem + 127) / 128, 128>>>(pred, targ, out,
                                                         rem_start, n);
    }
}

// round 11
// speedup vs baseline: 1.1144x; 1.0471x over previous
#include <cuda_runtime.h>
#include <math.h>

// ---------------- fast-math row loss (tolerance 1e-3, margin ~5e-8) --------
__device__ __forceinline__ float row_loss(const float* __restrict__ p,
                                          const float* __restrict__ t) {
    float dx = p[0] - t[0];
    float dy = p[1] - t[1];

    float wp = fminf(fmaxf(p[2], 1e-7f), 1e7f);
    float hp = fminf(fmaxf(p[3], 1e-7f), 1e7f);
    float ap = 0.25f * wp * wp;
    float bp = 0.25f * hp * hp;
    float sn, cs;
    __sincosf(p[4], &sn, &cs);           // |r| < pi/2: MUFU path accurate
    float c2 = cs * cs, s2 = sn * sn;
    float p00 = ap * c2 + bp * s2;
    float p11 = ap * s2 + bp * c2;
    float p01 = (ap - bp) * sn * cs;

    float wt = fminf(fmaxf(t[2], 1e-7f), 1e7f);
    float ht = fminf(fmaxf(t[3], 1e-7f), 1e7f);
    float at = 0.25f * wt * wt;
    float bt = 0.25f * ht * ht;
    float snt, cst;
    __sincosf(t[4], &snt, &cst);
    float ct2 = cst * cst, st2 = snt * snt;
    float t00 = at * ct2 + bt * st2;
    float t11 = at * st2 + bt * ct2;
    float t01 = (at - bt) * snt * cst;

    float det_p = p00 * p11 - p01 * p01;
    float det_t = t00 * t11 - t01 * t01;
    float inv_det_t = __fdividef(1.0f, det_t);

    float term1 = (dx * dx * t11 - 2.0f * dx * dy * t01 + dy * dy * t00) * inv_det_t;
    float tr = (t11 * p00 + t00 * p11 - 2.0f * t01 * p01) * inv_det_t;

    float dis = term1 + tr + __logf(__fdividef(det_t, det_p)) - 2.0f;
    float kl = fmaxf(dis, 1e-6f);
    float L = __logf(1.0f + kl);
    return __fdividef(L, 1.0f + L);      // 1 - 1/(1+L), tau = 1
}

// -------- warp-autonomous coalesced pipeline (no block sync) ----------------
// Each WARP independently double-buffers 32-row tiles through private smem.
// Loads: 40 lane-consecutive float4 per stream (coalesced: ~5 lines per warp
// LDG.128 instead of 20 for strided AoS -> 6x fewer L1tex wavefronts).
// Rows re-read from smem at word-stride 5 (gcd(5,32)=1: conflict-free).
// Only __syncwarp between stages — warps never wait on each other.
#define WTROWS 32
#define WTV4   40                        // 32*5/4 float4 per stream
#define WARPS_PER_CTA 8

__global__ void __launch_bounds__(256, 4)
kld_warpstage_kernel(const float4* __restrict__ pred,
                     const float4* __restrict__ targ,
                     float* __restrict__ out, int ntiles) {
    // [warp][double-buffer][stream][40 float4]
    __shared__ alignas(16) float4 sbuf[WARPS_PER_CTA][2][2][WTV4];

    const int tid  = threadIdx.x;
    const int wid  = tid >> 5;
    const int lane = tid & 31;
    const bool xl  = lane < (WTV4 - 32);          // lanes 0-7 load 2nd slot

    const long long gw     = (long long)blockIdx.x * WARPS_PER_CTA + wid;
    const long long nwarps = (long long)gridDim.x * WARPS_PER_CTA;
    if (gw >= ntiles) return;

    long long tile = gw;

    // ---- load tile 0 into regs (coalesced) ----
    size_t vb = (size_t)tile * WTV4;
    float4 p0 = __ldcs(&pred[vb + lane]);
    float4 t0 = __ldcs(&targ[vb + lane]);
    float4 p1 = {}, t1 = {};
    if (xl) { p1 = __ldcs(&pred[vb + 32 + lane]); t1 = __ldcs(&targ[vb + 32 + lane]); }

    // ---- stage tile 0 into buffer 0 ----
    sbuf[wid][0][0][lane] = p0;  sbuf[wid][0][1][lane] = t0;
    if (xl) { sbuf[wid][0][0][32 + lane] = p1;  sbuf[wid][0][1][32 + lane] = t1; }

    // ---- prefetch tile 1 into regs ----
    long long nt = tile + nwarps;
    bool hn = nt < ntiles;
    if (hn) {
        vb = (size_t)nt * WTV4;
        p0 = __ldcs(&pred[vb + lane]);
        t0 = __ldcs(&targ[vb + lane]);
        if (xl) { p1 = __ldcs(&pred[vb + 32 + lane]); t1 = __ldcs(&targ[vb + 32 + lane]); }
    }
    __syncwarp();

    int buf = 0;
#pragma unroll 1
    while (true) {
        // compute current tile from smem (stride-5 word reads: conflict-free)
        const float* pf = reinterpret_cast<const float*>(&sbuf[wid][buf][0][0]);
        const float* tf = reinterpret_cast<const float*>(&sbuf[wid][buf][1][0]);
        float r = row_loss(pf + 5 * lane, tf + 5 * lane);
        __stcs(&out[tile * WTROWS + lane], r);

        if (!hn) break;

        // stage prefetched tile into the other buffer (disjoint: no pre-sync)
        sbuf[wid][buf ^ 1][0][lane] = p0;  sbuf[wid][buf ^ 1][1][lane] = t0;
        if (xl) { sbuf[wid][buf ^ 1][0][32 + lane] = p1;
                  sbuf[wid][buf ^ 1][1][32 + lane] = t1; }

        // issue loads for the tile after next (hides under next compute)
        tile = nt;
        nt = tile + nwarps;
        hn = nt < ntiles;
        if (hn) {
            vb = (size_t)nt * WTV4;
            p0 = __ldcs(&pred[vb + lane]);
            t0 = __ldcs(&targ[vb + lane]);
            if (xl) { p1 = __ldcs(&pred[vb + 32 + lane]);
                      t1 = __ldcs(&targ[vb + 32 + lane]); }
        }
        __syncwarp();                     // STS visible within warp
        buf ^= 1;
    }
}

// Scalar tail for rows not covered by full 32-row tiles (not hit for N=4M).
__global__ void kld_loss_tail_kernel(const float* __restrict__ pred,
                                     const float* __restrict__ targ,
                                     float* __restrict__ out,
                                     int start, int n) {
    int i = start + blockIdx.x * blockDim.x + threadIdx.x;
    if (i >= n) return;
    out[i] = row_loss(pred + 5 * i, targ + 5 * i);
}

extern "C" void kernel_launch(void* const* d_in, const int* in_sizes, int n_in,
                              void* d_out, int out_size) {
    const float* pred = (const float*)d_in[0];
    const float* targ = (const float*)d_in[1];
    float* out = (float*)d_out;

    int n = in_sizes[0] / 5;            // rows
    int ntiles = n / WTROWS;            // 125000 for N=4M
    int rem_start = ntiles * WTROWS;

    if (ntiles > 0) {
        int grid = 152 * 4;             // persistent, 4 CTAs/SM
        long long maxg = ((long long)ntiles + WARPS_PER_CTA - 1) / WARPS_PER_CTA;
        if (grid > maxg) grid = (int)maxg;
        kld_warpstage_kernel<<<grid, 256>>>(
            (const float4*)pred, (const float4*)targ, out, ntiles);
    }
    if (rem_start < n) {
        int rem = n - rem_start;
        kld_loss_tail_kernel<<<(rem + 127) / 128, 128>>>(pred, targ, out,
                                                         rem_start, n);
    }
}